// round 9
// baseline (speedup 1.0000x reference)
#include <cuda_runtime.h>
#include <cuda_bf16.h>
#include <math.h>
#include <stdint.h>

#define SEQ   2048
#define ND    1024
#define NH    16
#define DH    64
#define NPOS  64

typedef __nv_bfloat16 bf16;
typedef __nv_bfloat162 bf162;

// ---------------- scratch (device globals: allocation-free) ----------------
__device__ float g_Q[SEQ * ND];                       // fp32 Q (li_kernel)
__device__ float g_li[NH * SEQ * NPOS];

__device__ bf16 g_inqh[SEQ * ND], g_inql[SEQ * ND];
__device__ bf16 g_inkh[SEQ * ND], g_inkl[SEQ * ND];
__device__ bf16 g_invh[SEQ * ND], g_invl[SEQ * ND];
__device__ bf16 g_wqh[ND * ND], g_wql[ND * ND];
__device__ bf16 g_wkh[ND * ND], g_wkl[ND * ND];
__device__ bf16 g_wvh[ND * ND], g_wvl[ND * ND];
__device__ bf16 g_woh[ND * ND], g_wol[ND * ND];
__device__ bf16 g_Qh[SEQ * ND], g_Ql[SEQ * ND];
__device__ bf16 g_Kh[SEQ * ND], g_Kl[SEQ * ND];
__device__ bf16 g_Vh[SEQ * ND], g_Vl[SEQ * ND];
__device__ bf16 g_ctxh[SEQ * ND], g_ctxl[SEQ * ND];

// ---------------- PTX helpers ----------------------------------------------
__device__ __forceinline__ uint32_t smem_u32(const void* p) {
    return (uint32_t)__cvta_generic_to_shared(p);
}
__device__ __forceinline__ void ldsm4(uint32_t* r, uint32_t a) {
    asm volatile("ldmatrix.sync.aligned.m8n8.x4.shared.b16 {%0,%1,%2,%3}, [%4];"
                 : "=r"(r[0]), "=r"(r[1]), "=r"(r[2]), "=r"(r[3]) : "r"(a));
}
__device__ __forceinline__ void ldsm4t(uint32_t* r, uint32_t a) {
    asm volatile("ldmatrix.sync.aligned.m8n8.x4.trans.shared.b16 {%0,%1,%2,%3}, [%4];"
                 : "=r"(r[0]), "=r"(r[1]), "=r"(r[2]), "=r"(r[3]) : "r"(a));
}
__device__ __forceinline__ void mma16816(float* c, const uint32_t* a, const uint32_t* b) {
    asm volatile(
        "mma.sync.aligned.m16n8k16.row.col.f32.bf16.bf16.f32 "
        "{%0,%1,%2,%3}, {%4,%5,%6,%7}, {%8,%9}, {%0,%1,%2,%3};"
        : "+f"(c[0]), "+f"(c[1]), "+f"(c[2]), "+f"(c[3])
        : "r"(a[0]), "r"(a[1]), "r"(a[2]), "r"(a[3]), "r"(b[0]), "r"(b[1]));
}

// ---------------- split fp32 -> bf16 hi + bf16 lo (batched) -----------------
__device__ __forceinline__ void split_body(const float* __restrict__ s,
                                           bf16* __restrict__ hi, bf16* __restrict__ lo)
{
    int i = (blockIdx.x * 256 + threadIdx.x) * 4;
    float4 v = *(const float4*)&s[i];
    bf16 h0 = __float2bfloat16_rn(v.x), h1 = __float2bfloat16_rn(v.y);
    bf16 h2 = __float2bfloat16_rn(v.z), h3 = __float2bfloat16_rn(v.w);
    bf16 l0 = __float2bfloat16_rn(v.x - __bfloat162float(h0));
    bf16 l1 = __float2bfloat16_rn(v.y - __bfloat162float(h1));
    bf16 l2 = __float2bfloat16_rn(v.z - __bfloat162float(h2));
    bf16 l3 = __float2bfloat16_rn(v.w - __bfloat162float(h3));
    *(bf162*)&hi[i]     = bf162{h0, h1};
    *(bf162*)&hi[i + 2] = bf162{h2, h3};
    *(bf162*)&lo[i]     = bf162{l0, l1};
    *(bf162*)&lo[i + 2] = bf162{l2, l3};
}

__global__ __launch_bounds__(256) void split3_kernel(
    const float* s0, const float* s1, const float* s2,
    bf16* h0, bf16* l0, bf16* h1, bf16* l1, bf16* h2, bf16* l2)
{
    const float* s = (blockIdx.y == 0) ? s0 : (blockIdx.y == 1) ? s1 : s2;
    bf16* hp = (blockIdx.y == 0) ? h0 : (blockIdx.y == 1) ? h1 : h2;
    bf16* lp = (blockIdx.y == 0) ? l0 : (blockIdx.y == 1) ? l1 : l2;
    split_body(s, hp, lp);
}

__global__ __launch_bounds__(256) void split4_kernel(
    const float* s0, const float* s1, const float* s2, const float* s3,
    bf16* h0, bf16* l0, bf16* h1, bf16* l1,
    bf16* h2, bf16* l2, bf16* h3, bf16* l3)
{
    const float* s = (blockIdx.y == 0) ? s0 : (blockIdx.y == 1) ? s1 :
                     (blockIdx.y == 2) ? s2 : s3;
    bf16* hp = (blockIdx.y == 0) ? h0 : (blockIdx.y == 1) ? h1 :
               (blockIdx.y == 2) ? h2 : h3;
    bf16* lp = (blockIdx.y == 0) ? l0 : (blockIdx.y == 1) ? l1 :
               (blockIdx.y == 2) ? l2 : l3;
    split_body(s, hp, lp);
}

// ---------------- Y = X @ W^T + bias (split-bf16 MMA) -----------------------
// Block 128x128, BK=32, 8 warps (warp tile 32x64), register-prefetch pipeline.
#define KST 40   // 32 + 8 pad

__global__ __launch_bounds__(256) void mm_bias_kernel(
    const bf16* __restrict__ Xh, const bf16* __restrict__ Xl,
    const bf16* __restrict__ Wh, const bf16* __restrict__ Wl,
    const float* __restrict__ bias,
    float* __restrict__ Yf, bf16* __restrict__ Yh, bf16* __restrict__ Yl)
{
    __shared__ bf16 Xsh[128][KST], Xsl[128][KST];
    __shared__ bf16 Wsh[128][KST], Wsl[128][KST];
    const int tid = threadIdx.x, lane = tid & 31, warp = tid >> 5;
    const int wm = warp & 3, wn = warp >> 2;
    const int m0 = blockIdx.y * 128, n0 = blockIdx.x * 128;

    const int xr = tid >> 2, xc = (tid & 3) * 8;

    uint4 pXh[2], pXl[2], pWh[2], pWl[2];

    #define MM_LOADG(kt)                                                         \
        { _Pragma("unroll") for (int it = 0; it < 2; it++) {                     \
            int r = xr + it * 64;                                                \
            pXh[it] = *(const uint4*)&Xh[(size_t)(m0 + r) * ND + (kt) + xc];     \
            pXl[it] = *(const uint4*)&Xl[(size_t)(m0 + r) * ND + (kt) + xc];     \
            pWh[it] = *(const uint4*)&Wh[(size_t)(n0 + r) * ND + (kt) + xc];     \
            pWl[it] = *(const uint4*)&Wl[(size_t)(n0 + r) * ND + (kt) + xc];     \
        } }
    #define MM_STORES()                                                          \
        { _Pragma("unroll") for (int it = 0; it < 2; it++) {                     \
            int r = xr + it * 64;                                                \
            *(uint4*)&Xsh[r][xc] = pXh[it]; *(uint4*)&Xsl[r][xc] = pXl[it];      \
            *(uint4*)&Wsh[r][xc] = pWh[it]; *(uint4*)&Wsl[r][xc] = pWl[it];      \
        } }

    float acc[2][8][4] = {};
    MM_LOADG(0); MM_STORES(); __syncthreads();

    for (int kt = 32; kt <= ND; kt += 32) {
        const bool more = (kt < ND);
        if (more) MM_LOADG(kt);
        #pragma unroll
        for (int kk = 0; kk < 32; kk += 16) {
            uint32_t Ah[2][4], Al[2][4];
            int arow = wm * 32 + (lane & 7) + ((lane >> 3) & 1) * 8;
            int acol = kk + (lane >> 4) * 8;
            ldsm4(Ah[0], smem_u32(&Xsh[arow][acol]));
            ldsm4(Ah[1], smem_u32(&Xsh[arow + 16][acol]));
            ldsm4(Al[0], smem_u32(&Xsl[arow][acol]));
            ldsm4(Al[1], smem_u32(&Xsl[arow + 16][acol]));
            #pragma unroll
            for (int nt2 = 0; nt2 < 4; nt2++) {
                uint32_t Bh[4], Bl[4];
                int brow = wn * 64 + nt2 * 16 + (lane >> 4) * 8 + (lane & 7);
                int bcol = kk + ((lane >> 3) & 1) * 8;
                ldsm4(Bh, smem_u32(&Wsh[brow][bcol]));
                ldsm4(Bl, smem_u32(&Wsl[brow][bcol]));
                #pragma unroll
                for (int mt = 0; mt < 2; mt++)
                    #pragma unroll
                    for (int p = 0; p < 2; p++) {
                        mma16816(acc[mt][nt2 * 2 + p], Ah[mt], &Bh[p * 2]);
                        mma16816(acc[mt][nt2 * 2 + p], Ah[mt], &Bl[p * 2]);
                        mma16816(acc[mt][nt2 * 2 + p], Al[mt], &Bh[p * 2]);
                    }
            }
        }
        __syncthreads();
        if (more) { MM_STORES(); __syncthreads(); }
    }

    const int r0 = lane >> 2, cc = (lane & 3) * 2;
    #pragma unroll
    for (int mt = 0; mt < 2; mt++)
        #pragma unroll
        for (int nt = 0; nt < 8; nt++) {
            int m = m0 + wm * 32 + mt * 16 + r0;
            int n = n0 + wn * 64 + nt * 8 + cc;
            float b0 = bias[n], b1 = bias[n + 1];
            float v0 = acc[mt][nt][0] + b0, v1 = acc[mt][nt][1] + b1;
            float v2 = acc[mt][nt][2] + b0, v3 = acc[mt][nt][3] + b1;
            if (Yf) {
                *(float2*)&Yf[(size_t)m * ND + n]       = float2{v0, v1};
                *(float2*)&Yf[(size_t)(m + 8) * ND + n] = float2{v2, v3};
            }
            if (Yh) {
                bf16 h0 = __float2bfloat16_rn(v0), h1 = __float2bfloat16_rn(v1);
                bf16 h2 = __float2bfloat16_rn(v2), h3 = __float2bfloat16_rn(v3);
                *(bf162*)&Yh[(size_t)m * ND + n]       = bf162{h0, h1};
                *(bf162*)&Yh[(size_t)(m + 8) * ND + n] = bf162{h2, h3};
                *(bf162*)&Yl[(size_t)m * ND + n] =
                    bf162{__float2bfloat16_rn(v0 - __bfloat162float(h0)),
                          __float2bfloat16_rn(v1 - __bfloat162float(h1))};
                *(bf162*)&Yl[(size_t)(m + 8) * ND + n] =
                    bf162{__float2bfloat16_rn(v2 - __bfloat162float(h2)),
                          __float2bfloat16_rn(v3 - __bfloat162float(h3))};
            }
        }
}

// -------- li[h,q,n] = sum_d Q[q, h*64+d] * pos_emb[d, n] --------------------
__global__ __launch_bounds__(256) void li_kernel(const float* __restrict__ pos_emb)
{
    __shared__ float Qs[64][65];
    __shared__ float Ps[64][65];
    const int tid = threadIdx.x;
    const int tx = tid & 15, ty = tid >> 4;
    const int h = blockIdx.y;
    const int q0 = blockIdx.x * 64;

    for (int i = tid; i < 64 * 64; i += 256) {
        int r = i >> 6, c = i & 63;
        Qs[r][c] = g_Q[(q0 + r) * ND + h * DH + c];
        Ps[r][c] = pos_emb[r * NPOS + c];
    }
    __syncthreads();

    float acc[4][4] = {};
    #pragma unroll 8
    for (int d = 0; d < 64; d++) {
        float a[4], b[4];
        #pragma unroll
        for (int i = 0; i < 4; i++) a[i] = Qs[ty * 4 + i][d];
        #pragma unroll
        for (int j = 0; j < 4; j++) b[j] = Ps[d][tx * 4 + j];
        #pragma unroll
        for (int i = 0; i < 4; i++)
            #pragma unroll
            for (int j = 0; j < 4; j++) acc[i][j] += a[i] * b[j];
    }
    #pragma unroll
    for (int i = 0; i < 4; i++)
        #pragma unroll
        for (int j = 0; j < 4; j++)
            g_li[(h * SEQ + q0 + ty * 4 + i) * NPOS + tx * 4 + j] = acc[i][j];
}

// ============ fused flash-style attention with CoPE (reverse key order) =====
// One CTA = 64 q-rows of one head; 256 threads / 8 warps; 2 CTAs/SM.
#define FA_STR  72                                 // bf16 tile stride
#define FA_QHOF 0
#define FA_QLOF (FA_QHOF + 64 * FA_STR * 2)        // Q region reused as li later
#define FA_KHOF (FA_QLOF + 64 * FA_STR * 2)
#define FA_KLOF (FA_KHOF + 64 * FA_STR * 2)
#define FA_VOF  (FA_KLOF + 64 * FA_STR * 2)        // [2 bufs][hi,lo]
#define FA_LOF  (FA_VOF + 4 * 64 * FA_STR * 2)     // logits fp32 64x68
#define FA_PHOF (FA_LOF + 64 * 68 * 4)
#define FA_PLOF (FA_PHOF + 64 * FA_STR * 2)
#define FA_STOF (FA_PLOF + 64 * FA_STR * 2)        // scale[64], dfin[64]
#define FA_SMEM (FA_STOF + 2 * 64 * 4)             // 110080 bytes

__global__ __launch_bounds__(256, 2) void fused_attn_kernel()
{
    extern __shared__ char sm[];
    bf16*  Qsh  = (bf16*)(sm + FA_QHOF);
    bf16*  Qsl  = (bf16*)(sm + FA_QLOF);
    float* lis  = (float*)(sm + FA_QHOF);          // overlay after frag build
    bf16*  Ksh  = (bf16*)(sm + FA_KHOF);
    bf16*  Ksl  = (bf16*)(sm + FA_KLOF);
    float* Lsm  = (float*)(sm + FA_LOF);
    bf16*  Psh  = (bf16*)(sm + FA_PHOF);
    bf16*  Psl  = (bf16*)(sm + FA_PLOF);
    float* scl  = (float*)(sm + FA_STOF);
    float* dfin = scl + 64;

    const int tid = threadIdx.x, lane = tid & 31, warp = tid >> 5;
    const int wm = warp & 3, wn = warp >> 2;       // QK/PV warp tile 16 x 32
    const int h = blockIdx.y, q0 = blockIdx.x * 64, ho = h * DH;

    const int lr = tid >> 2, lc = (tid & 3) * 16;  // tile loader mapping

    // ---- load Q tile ----
    *(uint4*)&Qsh[lr * FA_STR + lc]     = *(const uint4*)&g_Qh[(size_t)(q0 + lr) * ND + ho + lc];
    *(uint4*)&Qsh[lr * FA_STR + lc + 8] = *(const uint4*)&g_Qh[(size_t)(q0 + lr) * ND + ho + lc + 8];
    *(uint4*)&Qsl[lr * FA_STR + lc]     = *(const uint4*)&g_Ql[(size_t)(q0 + lr) * ND + ho + lc];
    *(uint4*)&Qsl[lr * FA_STR + lc + 8] = *(const uint4*)&g_Ql[(size_t)(q0 + lr) * ND + ho + lc + 8];
    __syncthreads();

    // ---- build persistent Q fragments (16 rows per warp, full DH=64) ----
    uint32_t QAh[4][4], QAl[4][4];
    {
        int ar = wm * 16 + (lane & 7) + ((lane >> 3) & 1) * 8;
        int ac = (lane >> 4) * 8;
        #pragma unroll
        for (int s = 0; s < 4; s++) {
            ldsm4(QAh[s], smem_u32(&Qsh[ar * FA_STR + s * 16 + ac]));
            ldsm4(QAl[s], smem_u32(&Qsl[ar * FA_STR + s * 16 + ac]));
        }
    }
    __syncthreads();

    // ---- overlay li + load first (last-key) chunk ----
    for (int i = tid; i < 64 * 64; i += 256)
        lis[i] = g_li[(size_t)(h * SEQ + q0 + (i >> 6)) * NPOS + (i & 63)];
    {
        int kn = 31 * 64 + lr;
        bf16* Vh0 = (bf16*)(sm + FA_VOF);
        bf16* Vl0 = Vh0 + 64 * FA_STR;
        *(uint4*)&Ksh[lr * FA_STR + lc]     = *(const uint4*)&g_Kh[(size_t)kn * ND + ho + lc];
        *(uint4*)&Ksh[lr * FA_STR + lc + 8] = *(const uint4*)&g_Kh[(size_t)kn * ND + ho + lc + 8];
        *(uint4*)&Ksl[lr * FA_STR + lc]     = *(const uint4*)&g_Kl[(size_t)kn * ND + ho + lc];
        *(uint4*)&Ksl[lr * FA_STR + lc + 8] = *(const uint4*)&g_Kl[(size_t)kn * ND + ho + lc + 8];
        *(uint4*)&Vh0[lr * FA_STR + lc]     = *(const uint4*)&g_Vh[(size_t)kn * ND + ho + lc];
        *(uint4*)&Vh0[lr * FA_STR + lc + 8] = *(const uint4*)&g_Vh[(size_t)kn * ND + ho + lc + 8];
        *(uint4*)&Vl0[lr * FA_STR + lc]     = *(const uint4*)&g_Vl[(size_t)kn * ND + ho + lc];
        *(uint4*)&Vl0[lr * FA_STR + lc + 8] = *(const uint4*)&g_Vl[(size_t)kn * ND + ho + lc + 8];
    }
    __syncthreads();

    float mreg[8], dreg[8], creg[8];
    #pragma unroll
    for (int i = 0; i < 8; i++) { mreg[i] = -INFINITY; dreg[i] = 0.0f; creg[i] = 0.0f; }
    float pacc[4][4] = {};
    int buf = 0;

    for (int ci = 31; ci >= 0; --ci) {
        const bool more = (ci > 0);
        uint4 pKh[2], pKl[2], pVh[2], pVl[2];
        if (more) {
            int kn = (ci - 1) * 64 + lr;
            pKh[0] = *(const uint4*)&g_Kh[(size_t)kn * ND + ho + lc];
            pKh[1] = *(const uint4*)&g_Kh[(size_t)kn * ND + ho + lc + 8];
            pKl[0] = *(const uint4*)&g_Kl[(size_t)kn * ND + ho + lc];
            pKl[1] = *(const uint4*)&g_Kl[(size_t)kn * ND + ho + lc + 8];
            pVh[0] = *(const uint4*)&g_Vh[(size_t)kn * ND + ho + lc];
            pVh[1] = *(const uint4*)&g_Vh[(size_t)kn * ND + ho + lc + 8];
            pVl[0] = *(const uint4*)&g_Vl[(size_t)kn * ND + ho + lc];
            pVl[1] = *(const uint4*)&g_Vl[(size_t)kn * ND + ho + lc + 8];
        }

        // ---- QK MMA: logits (x0.125) -> Lsm ----
        float qacc[4][4] = {};
        #pragma unroll
        for (int s = 0; s < 4; s++) {
            int kk = s * 16;
            #pragma unroll
            for (int nt2 = 0; nt2 < 2; nt2++) {
                uint32_t Bh[4], Bl[4];
                int br = wn * 32 + nt2 * 16 + (lane >> 4) * 8 + (lane & 7);
                int bc = kk + ((lane >> 3) & 1) * 8;
                ldsm4(Bh, smem_u32(&Ksh[br * FA_STR + bc]));
                ldsm4(Bl, smem_u32(&Ksl[br * FA_STR + bc]));
                #pragma unroll
                for (int p = 0; p < 2; p++) {
                    mma16816(qacc[nt2 * 2 + p], QAh[s], &Bh[p * 2]);
                    mma16816(qacc[nt2 * 2 + p], QAh[s], &Bl[p * 2]);
                    mma16816(qacc[nt2 * 2 + p], QAl[s], &Bh[p * 2]);
                }
            }
        }
        {
            int r = wm * 16 + (lane >> 2), cc = (lane & 3) * 2;
            #pragma unroll
            for (int nt = 0; nt < 4; nt++) {
                int c = wn * 32 + nt * 8 + cc;
                Lsm[r * 68 + c]           = qacc[nt][0] * 0.125f;
                Lsm[r * 68 + c + 1]       = qacc[nt][1] * 0.125f;
                Lsm[(r + 8) * 68 + c]     = qacc[nt][2] * 0.125f;
                Lsm[(r + 8) * 68 + c + 1] = qacc[nt][3] * 0.125f;
            }
        }
        __syncthreads();   // sync1: logits ready; K smem + V[buf^1] reads done

        if (more) {        // store next chunk (K, and V into other buffer)
            bf16* Vh = (bf16*)(sm + FA_VOF + (size_t)(buf ^ 1) * 2 * 64 * FA_STR * 2);
            bf16* Vl = Vh + 64 * FA_STR;
            *(uint4*)&Ksh[lr * FA_STR + lc]     = pKh[0];
            *(uint4*)&Ksh[lr * FA_STR + lc + 8] = pKh[1];
            *(uint4*)&Ksl[lr * FA_STR + lc]     = pKl[0];
            *(uint4*)&Ksl[lr * FA_STR + lc + 8] = pKl[1];
            *(uint4*)&Vh[lr * FA_STR + lc]      = pVh[0];
            *(uint4*)&Vh[lr * FA_STR + lc + 8]  = pVh[1];
            *(uint4*)&Vl[lr * FA_STR + lc]      = pVl[0];
            *(uint4*)&Vl[lr * FA_STR + lc + 8]  = pVl[1];
        }

        // ---- CoPE + online softmax: warp handles rows 8*warp..+7 ----
        #pragma unroll
        for (int rr = 0; rr < 8; rr++) {
            const int row = warp * 8 + rr;
            float2 lv = *(const float2*)&Lsm[row * 68 + lane * 2];
            float t0, t1;
            asm("tanh.approx.f32 %0, %1;" : "=f"(t0) : "f"(lv.x * 0.5f));
            asm("tanh.approx.f32 %0, %1;" : "=f"(t1) : "f"(lv.y * 0.5f));
            float g0 = fmaf(t0, 0.5f, 0.5f), g1 = fmaf(t1, 0.5f, 0.5f);
            float ps = g0 + g1;
            float s = ps;
            #pragma unroll
            for (int d = 1; d < 32; d <<= 1) {
                float n = __shfl_down_sync(0xffffffffu, s, d);
                if (lane < 32 - d) s += n;
            }
            float total = __shfl_sync(0xffffffffu, s, 0);
            float carry = creg[rr];
            float pos0 = fminf(carry + s, (float)(NPOS - 1));
            float pos1 = fminf(carry + s - g0, (float)(NPOS - 1));
            const float* li = &lis[row * 64];
            float pf0 = floorf(pos0), w0 = pos0 - pf0;
            float pf1 = floorf(pos1), w1 = pos1 - pf1;
            float cp0 = li[(int)ceilf(pos0)] * w0 + li[(int)pf0] * (1.0f - w0);
            float cp1 = li[(int)ceilf(pos1)] * w1 + li[(int)pf1] * (1.0f - w1);
            float x0 = lv.x + cp0, x1 = lv.y + cp1;
            float cm = fmaxf(x0, x1);
            #pragma unroll
            for (int d = 16; d > 0; d >>= 1)
                cm = fmaxf(cm, __shfl_xor_sync(0xffffffffu, cm, d));
            float mold = mreg[rr], mnew = fmaxf(mold, cm);
            float sc = __expf(mold - mnew);
            float p0 = __expf(x0 - mnew), p1 = __expf(x1 - mnew);
            float cs = p0 + p1;
            #pragma unroll
            for (int d = 16; d > 0; d >>= 1)
                cs += __shfl_xor_sync(0xffffffffu, cs, d);
            mreg[rr] = mnew;
            dreg[rr] = dreg[rr] * sc + cs;
            creg[rr] = carry + total;
            if (lane == 0) scl[row] = sc;
            bf16 hb0 = __float2bfloat16_rn(p0), hb1 = __float2bfloat16_rn(p1);
            *(bf162*)&Psh[row * FA_STR + lane * 2] = bf162{hb0, hb1};
            *(bf162*)&Psl[row * FA_STR + lane * 2] =
                bf162{__float2bfloat16_rn(p0 - __bfloat162float(hb0)),
                      __float2bfloat16_rn(p1 - __bfloat162float(hb1))};
        }
        __syncthreads();   // sync2: P + scale ready; new K/V stores visible

        // ---- PV MMA with accumulator rescale ----
        {
            int ra = wm * 16 + (lane >> 2);
            float s0 = scl[ra], s1 = scl[ra + 8];
            #pragma unroll
            for (int nt = 0; nt < 4; nt++) {
                pacc[nt][0] *= s0; pacc[nt][1] *= s0;
                pacc[nt][2] *= s1; pacc[nt][3] *= s1;
            }
        }
        bf16* Vh = (bf16*)(sm + FA_VOF + (size_t)buf * 2 * 64 * FA_STR * 2);
        bf16* Vl = Vh + 64 * FA_STR;
        #pragma unroll
        for (int s = 0; s < 4; s++) {
            int kk = s * 16;
            uint32_t Ah[4], Al[4];
            int ar = wm * 16 + (lane & 7) + ((lane >> 3) & 1) * 8;
            int ac = kk + (lane >> 4) * 8;
            ldsm4(Ah, smem_u32(&Psh[ar * FA_STR + ac]));
            ldsm4(Al, smem_u32(&Psl[ar * FA_STR + ac]));
            #pragma unroll
            for (int nt2 = 0; nt2 < 2; nt2++) {
                uint32_t Bh[4], Bl[4];
                int vr = kk + ((lane >> 3) & 1) * 8 + (lane & 7);
                int vc = wn * 32 + nt2 * 16 + (lane >> 4) * 8;
                ldsm4t(Bh, smem_u32(&Vh[vr * FA_STR + vc]));
                ldsm4t(Bl, smem_u32(&Vl[vr * FA_STR + vc]));
                #pragma unroll
                for (int p = 0; p < 2; p++) {
                    mma16816(pacc[nt2 * 2 + p], Ah, &Bh[p * 2]);
                    mma16816(pacc[nt2 * 2 + p], Ah, &Bl[p * 2]);
                    mma16816(pacc[nt2 * 2 + p], Al, &Bh[p * 2]);
                }
            }
        }
        buf ^= 1;
    }

    // ---- publish final denominators, normalize, write ctx hi/lo ----
    if (lane == 0) {
        #pragma unroll
        for (int rr = 0; rr < 8; rr++) dfin[warp * 8 + rr] = dreg[rr];
    }
    __syncthreads();
    {
        int r = wm * 16 + (lane >> 2), cc = (lane & 3) * 2;
        float i0 = 1.0f / dfin[r], i1 = 1.0f / dfin[r + 8];
        #pragma unroll
        for (int nt = 0; nt < 4; nt++) {
            int m = q0 + r, n = ho + wn * 32 + nt * 8 + cc;
            float v0 = pacc[nt][0] * i0, v1 = pacc[nt][1] * i0;
            float v2 = pacc[nt][2] * i1, v3 = pacc[nt][3] * i1;
            bf16 h0 = __float2bfloat16_rn(v0), h1 = __float2bfloat16_rn(v1);
            bf16 h2 = __float2bfloat16_rn(v2), h3 = __float2bfloat16_rn(v3);
            *(bf162*)&g_ctxh[(size_t)m * ND + n]       = bf162{h0, h1};
            *(bf162*)&g_ctxh[(size_t)(m + 8) * ND + n] = bf162{h2, h3};
            *(bf162*)&g_ctxl[(size_t)m * ND + n] =
                bf162{__float2bfloat16_rn(v0 - __bfloat162float(h0)),
                      __float2bfloat16_rn(v1 - __bfloat162float(h1))};
            *(bf162*)&g_ctxl[(size_t)(m + 8) * ND + n] =
                bf162{__float2bfloat16_rn(v2 - __bfloat162float(h2)),
                      __float2bfloat16_rn(v3 - __bfloat162float(h3))};
        }
    }
}

// ---------------------------------------------------------------------------
extern "C" void kernel_launch(void* const* d_in, const int* in_sizes, int n_in,
                              void* d_out, int out_size)
{
    const float* q      = (const float*)d_in[0];
    const float* k      = (const float*)d_in[1];
    const float* v      = (const float*)d_in[2];
    const float* Wq_w   = (const float*)d_in[3];
    const float* Wq_b   = (const float*)d_in[4];
    const float* Wk_w   = (const float*)d_in[5];
    const float* Wk_b   = (const float*)d_in[6];
    const float* Wv_w   = (const float*)d_in[7];
    const float* Wv_b   = (const float*)d_in[8];
    const float* Wo_w   = (const float*)d_in[9];
    const float* Wo_b   = (const float*)d_in[10];
    const float* pos_emb= (const float*)d_in[11];
    float* out = (float*)d_out;

    static bool attr_set = false;
    if (!attr_set) {
        cudaFuncSetAttribute(fused_attn_kernel,
                             cudaFuncAttributeMaxDynamicSharedMemorySize, FA_SMEM);
        attr_set = true;
    }

    bf16 *inqh, *inql, *inkh, *inkl, *invh, *invl;
    bf16 *wqh, *wql, *wkh, *wkl, *wvh, *wvl, *woh, *wol;
    bf16 *Qh, *Ql, *Kh, *Kl, *Vh, *Vl, *ctxh, *ctxl;
    float* Qf;
    cudaGetSymbolAddress((void**)&inqh, g_inqh); cudaGetSymbolAddress((void**)&inql, g_inql);
    cudaGetSymbolAddress((void**)&inkh, g_inkh); cudaGetSymbolAddress((void**)&inkl, g_inkl);
    cudaGetSymbolAddress((void**)&invh, g_invh); cudaGetSymbolAddress((void**)&invl, g_invl);
    cudaGetSymbolAddress((void**)&wqh, g_wqh);   cudaGetSymbolAddress((void**)&wql, g_wql);
    cudaGetSymbolAddress((void**)&wkh, g_wkh);   cudaGetSymbolAddress((void**)&wkl, g_wkl);
    cudaGetSymbolAddress((void**)&wvh, g_wvh);   cudaGetSymbolAddress((void**)&wvl, g_wvl);
    cudaGetSymbolAddress((void**)&woh, g_woh);   cudaGetSymbolAddress((void**)&wol, g_wol);
    cudaGetSymbolAddress((void**)&Qh, g_Qh);     cudaGetSymbolAddress((void**)&Ql, g_Ql);
    cudaGetSymbolAddress((void**)&Kh, g_Kh);     cudaGetSymbolAddress((void**)&Kl, g_Kl);
    cudaGetSymbolAddress((void**)&Vh, g_Vh);     cudaGetSymbolAddress((void**)&Vl, g_Vl);
    cudaGetSymbolAddress((void**)&ctxh, g_ctxh); cudaGetSymbolAddress((void**)&ctxl, g_ctxl);
    cudaGetSymbolAddress((void**)&Qf, g_Q);

    const int nIn = SEQ * ND / 1024;
    const int nW  = ND * ND / 1024;

    split3_kernel<<<dim3(nIn, 3), 256>>>(q, k, v,
                                         inqh, inql, inkh, inkl, invh, invl);
    split4_kernel<<<dim3(nW, 4), 256>>>(Wq_w, Wk_w, Wv_w, Wo_w,
                                        wqh, wql, wkh, wkl, wvh, wvl, woh, wol);

    dim3 gProj(ND / 128, SEQ / 128);   // (8, 16)
    mm_bias_kernel<<<gProj, 256>>>(inqh, inql, wqh, wql, Wq_b, Qf, Qh, Ql);
    mm_bias_kernel<<<gProj, 256>>>(inkh, inkl, wkh, wkl, Wk_b, nullptr, Kh, Kl);
    mm_bias_kernel<<<gProj, 256>>>(invh, invl, wvh, wvl, Wv_b, nullptr, Vh, Vl);

    li_kernel<<<dim3(SEQ / 64, NH), 256>>>(pos_emb);
    fused_attn_kernel<<<dim3(SEQ / 64, NH), 256, FA_SMEM>>>();

    mm_bias_kernel<<<gProj, 256>>>(ctxh, ctxl, woh, wol, Wo_b, out, nullptr, nullptr);
}

// round 10
// speedup vs baseline: 1.1257x; 1.1257x over previous
#include <cuda_runtime.h>
#include <cuda_bf16.h>
#include <math.h>
#include <stdint.h>

#define SEQ   2048
#define ND    1024
#define NH    16
#define DH    64
#define NPOS  64

typedef __nv_bfloat16 bf16;
typedef __nv_bfloat162 bf162;

// ---------------- scratch (device globals: allocation-free) ----------------
__device__ float g_Q[SEQ * ND];
__device__ float g_logits[(size_t)NH * SEQ * SEQ];    // 256 MB fp32 logits
__device__ float g_li[NH * SEQ * NPOS];

__device__ bf16 g_inqh[SEQ * ND], g_inql[SEQ * ND];
__device__ bf16 g_inkh[SEQ * ND], g_inkl[SEQ * ND];
__device__ bf16 g_invh[SEQ * ND], g_invl[SEQ * ND];
__device__ bf16 g_wqh[ND * ND], g_wql[ND * ND];
__device__ bf16 g_wkh[ND * ND], g_wkl[ND * ND];
__device__ bf16 g_wvh[ND * ND], g_wvl[ND * ND];
__device__ bf16 g_woh[ND * ND], g_wol[ND * ND];
__device__ bf16 g_Qh[SEQ * ND], g_Ql[SEQ * ND];
__device__ bf16 g_Kh[SEQ * ND], g_Kl[SEQ * ND];
__device__ bf16 g_Vh[SEQ * ND], g_Vl[SEQ * ND];
__device__ bf16 g_ctxh[SEQ * ND], g_ctxl[SEQ * ND];
__device__ bf16 g_Sh[(size_t)NH * SEQ * SEQ];
__device__ bf16 g_Sl[(size_t)NH * SEQ * SEQ];

// ---------------- PTX helpers ----------------------------------------------
__device__ __forceinline__ uint32_t smem_u32(const void* p) {
    return (uint32_t)__cvta_generic_to_shared(p);
}
__device__ __forceinline__ void ldsm4(uint32_t* r, uint32_t a) {
    asm volatile("ldmatrix.sync.aligned.m8n8.x4.shared.b16 {%0,%1,%2,%3}, [%4];"
                 : "=r"(r[0]), "=r"(r[1]), "=r"(r[2]), "=r"(r[3]) : "r"(a));
}
__device__ __forceinline__ void ldsm4t(uint32_t* r, uint32_t a) {
    asm volatile("ldmatrix.sync.aligned.m8n8.x4.trans.shared.b16 {%0,%1,%2,%3}, [%4];"
                 : "=r"(r[0]), "=r"(r[1]), "=r"(r[2]), "=r"(r[3]) : "r"(a));
}
__device__ __forceinline__ void mma16816(float* c, const uint32_t* a, const uint32_t* b) {
    asm volatile(
        "mma.sync.aligned.m16n8k16.row.col.f32.bf16.bf16.f32 "
        "{%0,%1,%2,%3}, {%4,%5,%6,%7}, {%8,%9}, {%0,%1,%2,%3};"
        : "+f"(c[0]), "+f"(c[1]), "+f"(c[2]), "+f"(c[3])
        : "r"(a[0]), "r"(a[1]), "r"(a[2]), "r"(a[3]), "r"(b[0]), "r"(b[1]));
}
__device__ __forceinline__ void cp16(uint32_t sa, const void* g) {
    asm volatile("cp.async.cg.shared.global [%0], [%1], 16;" :: "r"(sa), "l"(g));
}
#define CP_COMMIT() asm volatile("cp.async.commit_group;" ::: "memory")
#define CP_WAIT1()  asm volatile("cp.async.wait_group 1;" ::: "memory")
#define CP_WAIT0()  asm volatile("cp.async.wait_group 0;" ::: "memory")

// ---------------- split fp32 -> bf16 hi + bf16 lo (batched) -----------------
__device__ __forceinline__ void split_body(const float* __restrict__ s,
                                           bf16* __restrict__ hi, bf16* __restrict__ lo)
{
    int i = (blockIdx.x * 256 + threadIdx.x) * 4;
    float4 v = *(const float4*)&s[i];
    bf16 h0 = __float2bfloat16_rn(v.x), h1 = __float2bfloat16_rn(v.y);
    bf16 h2 = __float2bfloat16_rn(v.z), h3 = __float2bfloat16_rn(v.w);
    bf16 l0 = __float2bfloat16_rn(v.x - __bfloat162float(h0));
    bf16 l1 = __float2bfloat16_rn(v.y - __bfloat162float(h1));
    bf16 l2 = __float2bfloat16_rn(v.z - __bfloat162float(h2));
    bf16 l3 = __float2bfloat16_rn(v.w - __bfloat162float(h3));
    *(bf162*)&hi[i]     = bf162{h0, h1};
    *(bf162*)&hi[i + 2] = bf162{h2, h3};
    *(bf162*)&lo[i]     = bf162{l0, l1};
    *(bf162*)&lo[i + 2] = bf162{l2, l3};
}

__global__ __launch_bounds__(256) void split3_kernel(
    const float* s0, const float* s1, const float* s2,
    bf16* h0, bf16* l0, bf16* h1, bf16* l1, bf16* h2, bf16* l2)
{
    const float* s = (blockIdx.y == 0) ? s0 : (blockIdx.y == 1) ? s1 : s2;
    bf16* hp = (blockIdx.y == 0) ? h0 : (blockIdx.y == 1) ? h1 : h2;
    bf16* lp = (blockIdx.y == 0) ? l0 : (blockIdx.y == 1) ? l1 : l2;
    split_body(s, hp, lp);
}

__global__ __launch_bounds__(256) void split4_kernel(
    const float* s0, const float* s1, const float* s2, const float* s3,
    bf16* h0, bf16* l0, bf16* h1, bf16* l1,
    bf16* h2, bf16* l2, bf16* h3, bf16* l3)
{
    const float* s = (blockIdx.y == 0) ? s0 : (blockIdx.y == 1) ? s1 :
                     (blockIdx.y == 2) ? s2 : s3;
    bf16* hp = (blockIdx.y == 0) ? h0 : (blockIdx.y == 1) ? h1 :
               (blockIdx.y == 2) ? h2 : h3;
    bf16* lp = (blockIdx.y == 0) ? l0 : (blockIdx.y == 1) ? l1 :
               (blockIdx.y == 2) ? l2 : l3;
    split_body(s, hp, lp);
}

// ---------------- Y = X @ W^T + bias (split-bf16, cp.async 2-stage) ---------
// Block 128(m) x 64(n), BK=32, 8 warps (warp tile 32x32). grid 256 => 2 CTA/SM.
#define MMST 40
#define MM_XH 0
#define MM_XL (128 * MMST)
#define MM_WH (256 * MMST)
#define MM_WL (320 * MMST)
#define MM_STAGE (384 * MMST)            // elems per stage
#define MM_SMEM  (2 * MM_STAGE * 2)      // 61440 bytes

__global__ __launch_bounds__(256, 2) void mm_bias_kernel(
    const bf16* __restrict__ Xh, const bf16* __restrict__ Xl,
    const bf16* __restrict__ Wh, const bf16* __restrict__ Wl,
    const float* __restrict__ bias,
    float* __restrict__ Yf, bf16* __restrict__ Yh, bf16* __restrict__ Yl)
{
    extern __shared__ bf16 mms[];
    const int tid = threadIdx.x, lane = tid & 31, warp = tid >> 5;
    const int wm = warp & 3, wn = warp >> 2;
    const int m0 = blockIdx.y * 128, n0 = blockIdx.x * 64;
    const int xr = tid >> 2, xc = (tid & 3) * 8;

    #define MM_LOAD(kt, s)                                                        \
        { bf16* st = mms + (s) * MM_STAGE;                                        \
          cp16(smem_u32(&st[MM_XH + xr * MMST + xc]),                             \
               &Xh[(size_t)(m0 + xr) * ND + (kt) + xc]);                          \
          cp16(smem_u32(&st[MM_XH + (xr + 64) * MMST + xc]),                      \
               &Xh[(size_t)(m0 + xr + 64) * ND + (kt) + xc]);                     \
          cp16(smem_u32(&st[MM_XL + xr * MMST + xc]),                             \
               &Xl[(size_t)(m0 + xr) * ND + (kt) + xc]);                          \
          cp16(smem_u32(&st[MM_XL + (xr + 64) * MMST + xc]),                      \
               &Xl[(size_t)(m0 + xr + 64) * ND + (kt) + xc]);                     \
          cp16(smem_u32(&st[MM_WH + xr * MMST + xc]),                             \
               &Wh[(size_t)(n0 + xr) * ND + (kt) + xc]);                          \
          cp16(smem_u32(&st[MM_WL + xr * MMST + xc]),                             \
               &Wl[(size_t)(n0 + xr) * ND + (kt) + xc]);                          \
          CP_COMMIT(); }

    float acc[2][4][4] = {};
    MM_LOAD(0, 0);
    int s = 0;
    for (int kt = 0; kt < ND; kt += 32) {
        if (kt + 32 < ND) { MM_LOAD(kt + 32, s ^ 1); CP_WAIT1(); }
        else              { CP_WAIT0(); }
        __syncthreads();
        bf16* st = mms + s * MM_STAGE;
        #pragma unroll
        for (int kk = 0; kk < 32; kk += 16) {
            uint32_t Ah[2][4], Al[2][4];
            int arow = wm * 32 + (lane & 7) + ((lane >> 3) & 1) * 8;
            int acol = kk + (lane >> 4) * 8;
            ldsm4(Ah[0], smem_u32(&st[MM_XH + arow * MMST + acol]));
            ldsm4(Ah[1], smem_u32(&st[MM_XH + (arow + 16) * MMST + acol]));
            ldsm4(Al[0], smem_u32(&st[MM_XL + arow * MMST + acol]));
            ldsm4(Al[1], smem_u32(&st[MM_XL + (arow + 16) * MMST + acol]));
            #pragma unroll
            for (int nt2 = 0; nt2 < 2; nt2++) {
                uint32_t Bh[4], Bl[4];
                int brow = wn * 32 + nt2 * 16 + (lane >> 4) * 8 + (lane & 7);
                int bcol = kk + ((lane >> 3) & 1) * 8;
                ldsm4(Bh, smem_u32(&st[MM_WH + brow * MMST + bcol]));
                ldsm4(Bl, smem_u32(&st[MM_WL + brow * MMST + bcol]));
                #pragma unroll
                for (int mt = 0; mt < 2; mt++)
                    #pragma unroll
                    for (int p = 0; p < 2; p++) {
                        mma16816(acc[mt][nt2 * 2 + p], Ah[mt], &Bh[p * 2]);
                        mma16816(acc[mt][nt2 * 2 + p], Ah[mt], &Bl[p * 2]);
                        mma16816(acc[mt][nt2 * 2 + p], Al[mt], &Bh[p * 2]);
                    }
            }
        }
        __syncthreads();
        s ^= 1;
    }

    const int r0 = lane >> 2, cc = (lane & 3) * 2;
    #pragma unroll
    for (int mt = 0; mt < 2; mt++)
        #pragma unroll
        for (int nt = 0; nt < 4; nt++) {
            int m = m0 + wm * 32 + mt * 16 + r0;
            int n = n0 + wn * 32 + nt * 8 + cc;
            float b0 = bias[n], b1 = bias[n + 1];
            float v0 = acc[mt][nt][0] + b0, v1 = acc[mt][nt][1] + b1;
            float v2 = acc[mt][nt][2] + b0, v3 = acc[mt][nt][3] + b1;
            if (Yf) {
                *(float2*)&Yf[(size_t)m * ND + n]       = float2{v0, v1};
                *(float2*)&Yf[(size_t)(m + 8) * ND + n] = float2{v2, v3};
            }
            if (Yh) {
                bf16 h0 = __float2bfloat16_rn(v0), h1 = __float2bfloat16_rn(v1);
                bf16 h2 = __float2bfloat16_rn(v2), h3 = __float2bfloat16_rn(v3);
                *(bf162*)&Yh[(size_t)m * ND + n]       = bf162{h0, h1};
                *(bf162*)&Yh[(size_t)(m + 8) * ND + n] = bf162{h2, h3};
                *(bf162*)&Yl[(size_t)m * ND + n] =
                    bf162{__float2bfloat16_rn(v0 - __bfloat162float(h0)),
                          __float2bfloat16_rn(v1 - __bfloat162float(h1))};
                *(bf162*)&Yl[(size_t)(m + 8) * ND + n] =
                    bf162{__float2bfloat16_rn(v2 - __bfloat162float(h2)),
                          __float2bfloat16_rn(v3 - __bfloat162float(h3))};
            }
        }
}

// ---------------- logits = 0.125 * Q K^T (per head) -------------------------
// Block 128(q) x 128(keys), whole DH=64 resident, warp tile 32x64. Dyn smem.
#define QKS 72
#define QK_QH 0
#define QK_QL (QK_QH + 128 * QKS * 2)
#define QK_KH (QK_QL + 128 * QKS * 2)
#define QK_KL (QK_KH + 128 * QKS * 2)
#define QK_SMEM (QK_KL + 128 * QKS * 2)

__global__ __launch_bounds__(256) void qk_kernel()
{
    extern __shared__ char sm[];
    bf16* Qsh = (bf16*)(sm + QK_QH);
    bf16* Qsl = (bf16*)(sm + QK_QL);
    bf16* Ksh = (bf16*)(sm + QK_KH);
    bf16* Ksl = (bf16*)(sm + QK_KL);

    const int tid = threadIdx.x, lane = tid & 31, warp = tid >> 5;
    const int wm = warp & 3, wn = warp >> 2;
    const int h = blockIdx.z;
    const int q0 = blockIdx.y * 128, k0 = blockIdx.x * 128;
    const int ho = h * DH;

    const int lr = tid >> 2, lc = (tid & 3) * 16;
    #pragma unroll
    for (int it = 0; it < 2; it++) {
        int r = lr + it * 64;
        *(uint4*)&Qsh[r * QKS + lc]     = *(const uint4*)&g_Qh[(size_t)(q0 + r) * ND + ho + lc];
        *(uint4*)&Qsh[r * QKS + lc + 8] = *(const uint4*)&g_Qh[(size_t)(q0 + r) * ND + ho + lc + 8];
        *(uint4*)&Qsl[r * QKS + lc]     = *(const uint4*)&g_Ql[(size_t)(q0 + r) * ND + ho + lc];
        *(uint4*)&Qsl[r * QKS + lc + 8] = *(const uint4*)&g_Ql[(size_t)(q0 + r) * ND + ho + lc + 8];
        *(uint4*)&Ksh[r * QKS + lc]     = *(const uint4*)&g_Kh[(size_t)(k0 + r) * ND + ho + lc];
        *(uint4*)&Ksh[r * QKS + lc + 8] = *(const uint4*)&g_Kh[(size_t)(k0 + r) * ND + ho + lc + 8];
        *(uint4*)&Ksl[r * QKS + lc]     = *(const uint4*)&g_Kl[(size_t)(k0 + r) * ND + ho + lc];
        *(uint4*)&Ksl[r * QKS + lc + 8] = *(const uint4*)&g_Kl[(size_t)(k0 + r) * ND + ho + lc + 8];
    }
    __syncthreads();

    float acc[2][8][4] = {};
    #pragma unroll
    for (int kk = 0; kk < 64; kk += 16) {
        uint32_t Ah[2][4], Al[2][4];
        int arow = wm * 32 + (lane & 7) + ((lane >> 3) & 1) * 8;
        int acol = kk + (lane >> 4) * 8;
        ldsm4(Ah[0], smem_u32(&Qsh[arow * QKS + acol]));
        ldsm4(Ah[1], smem_u32(&Qsh[(arow + 16) * QKS + acol]));
        ldsm4(Al[0], smem_u32(&Qsl[arow * QKS + acol]));
        ldsm4(Al[1], smem_u32(&Qsl[(arow + 16) * QKS + acol]));
        #pragma unroll
        for (int nt2 = 0; nt2 < 4; nt2++) {
            uint32_t Bh[4], Bl[4];
            int brow = wn * 64 + nt2 * 16 + (lane >> 4) * 8 + (lane & 7);
            int bcol = kk + ((lane >> 3) & 1) * 8;
            ldsm4(Bh, smem_u32(&Ksh[brow * QKS + bcol]));
            ldsm4(Bl, smem_u32(&Ksl[brow * QKS + bcol]));
            #pragma unroll
            for (int mt = 0; mt < 2; mt++)
                #pragma unroll
                for (int p = 0; p < 2; p++) {
                    mma16816(acc[mt][nt2 * 2 + p], Ah[mt], &Bh[p * 2]);
                    mma16816(acc[mt][nt2 * 2 + p], Ah[mt], &Bl[p * 2]);
                    mma16816(acc[mt][nt2 * 2 + p], Al[mt], &Bh[p * 2]);
                }
        }
    }

    float* out = g_logits + (size_t)h * SEQ * SEQ;
    const int r0 = lane >> 2, cc = (lane & 3) * 2;
    #pragma unroll
    for (int mt = 0; mt < 2; mt++)
        #pragma unroll
        for (int nt = 0; nt < 8; nt++) {
            int m = q0 + wm * 32 + mt * 16 + r0;
            int n = k0 + wn * 64 + nt * 8 + cc;
            *(float2*)&out[(size_t)m * SEQ + n] =
                float2{acc[mt][nt][0] * 0.125f, acc[mt][nt][1] * 0.125f};
            *(float2*)&out[(size_t)(m + 8) * SEQ + n] =
                float2{acc[mt][nt][2] * 0.125f, acc[mt][nt][3] * 0.125f};
        }
}

// -------- li[h,q,n] = sum_d Q[q, h*64+d] * pos_emb[d, n] --------------------
__global__ __launch_bounds__(256) void li_kernel(const float* __restrict__ pos_emb)
{
    __shared__ float Qs[64][65];
    __shared__ float Ps[64][65];
    const int tid = threadIdx.x;
    const int tx = tid & 15, ty = tid >> 4;
    const int h = blockIdx.y;
    const int q0 = blockIdx.x * 64;

    for (int i = tid; i < 64 * 64; i += 256) {
        int r = i >> 6, c = i & 63;
        Qs[r][c] = g_Q[(q0 + r) * ND + h * DH + c];
        Ps[r][c] = pos_emb[r * NPOS + c];
    }
    __syncthreads();

    float acc[4][4] = {};
    #pragma unroll 8
    for (int d = 0; d < 64; d++) {
        float a[4], b[4];
        #pragma unroll
        for (int i = 0; i < 4; i++) a[i] = Qs[ty * 4 + i][d];
        #pragma unroll
        for (int j = 0; j < 4; j++) b[j] = Ps[d][tx * 4 + j];
        #pragma unroll
        for (int i = 0; i < 4; i++)
            #pragma unroll
            for (int j = 0; j < 4; j++) acc[i][j] += a[i] * b[j];
    }
    #pragma unroll
    for (int i = 0; i < 4; i++)
        #pragma unroll
        for (int j = 0; j < 4; j++)
            g_li[(h * SEQ + q0 + ty * 4 + i) * NPOS + tx * 4 + j] = acc[i][j];
}

// -------- per (h,q) row: gates -> suffix-cumsum -> CoPE -> softmax ----------
__global__ __launch_bounds__(256) void cope_softmax_kernel()
{
    __shared__ float li[NPOS];
    __shared__ float wsum[8];
    __shared__ float redm[8];
    __shared__ float reds[8];

    const int tid = threadIdx.x;
    const int lane = tid & 31, warp = tid >> 5;
    const int q = blockIdx.x, h = blockIdx.y;
    const size_t rbase = ((size_t)h * SEQ + q) * SEQ;
    const float* lrow = g_logits + rbase;

    if (tid < NPOS) li[tid] = g_li[(h * SEQ + q) * NPOS + tid];

    const int base = tid * 8;
    float x[8];
    *(float4*)&x[0] = *(const float4*)&lrow[base];
    *(float4*)&x[4] = *(const float4*)&lrow[base + 4];

    float g[8];
    float csum = 0.0f;
    #pragma unroll
    for (int j = 7; j >= 0; --j) {
        float t;
        asm("tanh.approx.f32 %0, %1;" : "=f"(t) : "f"(x[j] * 0.5f));
        csum += fmaf(t, 0.5f, 0.5f);
        g[j] = csum;
    }
    float v = csum;
    #pragma unroll
    for (int d = 1; d < 32; d <<= 1) {
        float n = __shfl_up_sync(0xffffffffu, v, d);
        if (lane >= d) v += n;
    }
    if (lane == 31) wsum[warp] = v;
    __syncthreads();
    float wpre = 0.0f, total = 0.0f;
    #pragma unroll
    for (int w = 0; w < 8; w++) {
        float s = wsum[w];
        if (w < warp) wpre += s;
        total += s;
    }
    const float off = total - (wpre + v);

    float lmax = -INFINITY;
    #pragma unroll
    for (int j = 0; j < 8; j++) {
        float pos = fminf(g[j] + off, (float)(NPOS - 1));
        float pf = floorf(pos);
        int fi = (int)pf;
        int ci = (int)ceilf(pos);
        float w = pos - pf;
        x[j] += li[ci] * w + li[fi] * (1.0f - w);
        lmax = fmaxf(lmax, x[j]);
    }
    #pragma unroll
    for (int d = 16; d > 0; d >>= 1)
        lmax = fmaxf(lmax, __shfl_xor_sync(0xffffffffu, lmax, d));
    if (lane == 0) redm[warp] = lmax;
    __syncthreads();
    float mx = redm[0];
    #pragma unroll
    for (int w = 1; w < 8; w++) mx = fmaxf(mx, redm[w]);

    float lsum = 0.0f;
    #pragma unroll
    for (int j = 0; j < 8; j++) {
        x[j] = __expf(x[j] - mx);
        lsum += x[j];
    }
    #pragma unroll
    for (int d = 16; d > 0; d >>= 1)
        lsum += __shfl_xor_sync(0xffffffffu, lsum, d);
    if (lane == 0) reds[warp] = lsum;
    __syncthreads();
    float tsum = 0.0f;
    #pragma unroll
    for (int w = 0; w < 8; w++) tsum += reds[w];
    const float inv = 1.0f / tsum;

    bf16* sh = g_Sh + rbase + base;
    bf16* sl = g_Sl + rbase + base;
    #pragma unroll
    for (int jp = 0; jp < 4; jp++) {
        float a = x[2 * jp] * inv, b = x[2 * jp + 1] * inv;
        bf16 ha = __float2bfloat16_rn(a), hb = __float2bfloat16_rn(b);
        ((bf162*)sh)[jp] = bf162{ha, hb};
        ((bf162*)sl)[jp] = bf162{__float2bfloat16_rn(a - __bfloat162float(ha)),
                                 __float2bfloat16_rn(b - __bfloat162float(hb))};
    }
}

// -------- ctx = scores @ V (split-bf16, cp.async 2-stage) -------------------
// Block 128(q) x 64(n=head), BK=32, 8 warps (32x32). grid (16,16)=256 CTAs.
#define CXST  40
#define CXVST 72
#define CX_SH 0
#define CX_SL (128 * CXST)
#define CX_VH (256 * CXST)
#define CX_VL (256 * CXST + 32 * CXVST)
#define CX_STAGE (256 * CXST + 64 * CXVST)   // elems
#define CX_SMEM  (2 * CX_STAGE * 2)          // 59392 bytes

__global__ __launch_bounds__(256, 2) void ctx_kernel()
{
    extern __shared__ bf16 cxs[];
    const int tid = threadIdx.x, lane = tid & 31, warp = tid >> 5;
    const int wm = warp & 3, wn = warp >> 2;
    const int h = blockIdx.y;
    const int q0 = blockIdx.x * 128;
    const int ho = h * DH;
    const bf16* Sh = g_Sh + (size_t)h * SEQ * SEQ;
    const bf16* Sl = g_Sl + (size_t)h * SEQ * SEQ;

    const int sr = tid >> 1, sc = (tid & 1) * 16;
    const int vr = tid >> 3, vc = (tid & 7) * 8;

    #define CX_LOAD(kt, s)                                                        \
        { bf16* st = cxs + (s) * CX_STAGE;                                        \
          cp16(smem_u32(&st[CX_SH + sr * CXST + sc]),                             \
               &Sh[(size_t)(q0 + sr) * SEQ + (kt) + sc]);                         \
          cp16(smem_u32(&st[CX_SH + sr * CXST + sc + 8]),                         \
               &Sh[(size_t)(q0 + sr) * SEQ + (kt) + sc + 8]);                     \
          cp16(smem_u32(&st[CX_SL + sr * CXST + sc]),                             \
               &Sl[(size_t)(q0 + sr) * SEQ + (kt) + sc]);                         \
          cp16(smem_u32(&st[CX_SL + sr * CXST + sc + 8]),                         \
               &Sl[(size_t)(q0 + sr) * SEQ + (kt) + sc + 8]);                     \
          cp16(smem_u32(&st[CX_VH + vr * CXVST + vc]),                            \
               &g_Vh[(size_t)((kt) + vr) * ND + ho + vc]);                        \
          cp16(smem_u32(&st[CX_VL + vr * CXVST + vc]),                            \
               &g_Vl[(size_t)((kt) + vr) * ND + ho + vc]);                        \
          CP_COMMIT(); }

    float acc[2][4][4] = {};
    CX_LOAD(0, 0);
    int s = 0;
    for (int kt = 0; kt < SEQ; kt += 32) {
        if (kt + 32 < SEQ) { CX_LOAD(kt + 32, s ^ 1); CP_WAIT1(); }
        else               { CP_WAIT0(); }
        __syncthreads();
        bf16* st = cxs + s * CX_STAGE;
        #pragma unroll
        for (int kk = 0; kk < 32; kk += 16) {
            uint32_t Ah[2][4], Al[2][4];
            int arow = wm * 32 + (lane & 7) + ((lane >> 3) & 1) * 8;
            int acol = kk + (lane >> 4) * 8;
            ldsm4(Ah[0], smem_u32(&st[CX_SH + arow * CXST + acol]));
            ldsm4(Ah[1], smem_u32(&st[CX_SH + (arow + 16) * CXST + acol]));
            ldsm4(Al[0], smem_u32(&st[CX_SL + arow * CXST + acol]));
            ldsm4(Al[1], smem_u32(&st[CX_SL + (arow + 16) * CXST + acol]));
            #pragma unroll
            for (int nt2 = 0; nt2 < 2; nt2++) {
                uint32_t Bh[4], Bl[4];
                int vrow = kk + ((lane >> 3) & 1) * 8 + (lane & 7);
                int vcol = wn * 32 + nt2 * 16 + (lane >> 4) * 8;
                ldsm4t(Bh, smem_u32(&st[CX_VH + vrow * CXVST + vcol]));
                ldsm4t(Bl, smem_u32(&st[CX_VL + vrow * CXVST + vcol]));
                #pragma unroll
                for (int mt = 0; mt < 2; mt++)
                    #pragma unroll
                    for (int p = 0; p < 2; p++) {
                        mma16816(acc[mt][nt2 * 2 + p], Ah[mt], &Bh[p * 2]);
                        mma16816(acc[mt][nt2 * 2 + p], Ah[mt], &Bl[p * 2]);
                        mma16816(acc[mt][nt2 * 2 + p], Al[mt], &Bh[p * 2]);
                    }
            }
        }
        __syncthreads();
        s ^= 1;
    }

    const int r0 = lane >> 2, cc = (lane & 3) * 2;
    #pragma unroll
    for (int mt = 0; mt < 2; mt++)
        #pragma unroll
        for (int nt = 0; nt < 4; nt++) {
            int m = q0 + wm * 32 + mt * 16 + r0;
            int n = ho + wn * 32 + nt * 8 + cc;
            float v0 = acc[mt][nt][0], v1 = acc[mt][nt][1];
            float v2 = acc[mt][nt][2], v3 = acc[mt][nt][3];
            bf16 h0 = __float2bfloat16_rn(v0), h1 = __float2bfloat16_rn(v1);
            bf16 h2 = __float2bfloat16_rn(v2), h3 = __float2bfloat16_rn(v3);
            *(bf162*)&g_ctxh[(size_t)m * ND + n]       = bf162{h0, h1};
            *(bf162*)&g_ctxh[(size_t)(m + 8) * ND + n] = bf162{h2, h3};
            *(bf162*)&g_ctxl[(size_t)m * ND + n] =
                bf162{__float2bfloat16_rn(v0 - __bfloat162float(h0)),
                      __float2bfloat16_rn(v1 - __bfloat162float(h1))};
            *(bf162*)&g_ctxl[(size_t)(m + 8) * ND + n] =
                bf162{__float2bfloat16_rn(v2 - __bfloat162float(h2)),
                      __float2bfloat16_rn(v3 - __bfloat162float(h3))};
        }
}

// ---------------------------------------------------------------------------
extern "C" void kernel_launch(void* const* d_in, const int* in_sizes, int n_in,
                              void* d_out, int out_size)
{
    const float* q      = (const float*)d_in[0];
    const float* k      = (const float*)d_in[1];
    const float* v      = (const float*)d_in[2];
    const float* Wq_w   = (const float*)d_in[3];
    const float* Wq_b   = (const float*)d_in[4];
    const float* Wk_w   = (const float*)d_in[5];
    const float* Wk_b   = (const float*)d_in[6];
    const float* Wv_w   = (const float*)d_in[7];
    const float* Wv_b   = (const float*)d_in[8];
    const float* Wo_w   = (const float*)d_in[9];
    const float* Wo_b   = (const float*)d_in[10];
    const float* pos_emb= (const float*)d_in[11];
    float* out = (float*)d_out;

    static bool attr_set = false;
    if (!attr_set) {
        cudaFuncSetAttribute(mm_bias_kernel,
                             cudaFuncAttributeMaxDynamicSharedMemorySize, MM_SMEM);
        cudaFuncSetAttribute(qk_kernel,
                             cudaFuncAttributeMaxDynamicSharedMemorySize, QK_SMEM);
        cudaFuncSetAttribute(ctx_kernel,
                             cudaFuncAttributeMaxDynamicSharedMemorySize, CX_SMEM);
        attr_set = true;
    }

    bf16 *inqh, *inql, *inkh, *inkl, *invh, *invl;
    bf16 *wqh, *wql, *wkh, *wkl, *wvh, *wvl, *woh, *wol;
    bf16 *Qh, *Ql, *Kh, *Kl, *Vh, *Vl, *ctxh, *ctxl;
    float* Qf;
    cudaGetSymbolAddress((void**)&inqh, g_inqh); cudaGetSymbolAddress((void**)&inql, g_inql);
    cudaGetSymbolAddress((void**)&inkh, g_inkh); cudaGetSymbolAddress((void**)&inkl, g_inkl);
    cudaGetSymbolAddress((void**)&invh, g_invh); cudaGetSymbolAddress((void**)&invl, g_invl);
    cudaGetSymbolAddress((void**)&wqh, g_wqh);   cudaGetSymbolAddress((void**)&wql, g_wql);
    cudaGetSymbolAddress((void**)&wkh, g_wkh);   cudaGetSymbolAddress((void**)&wkl, g_wkl);
    cudaGetSymbolAddress((void**)&wvh, g_wvh);   cudaGetSymbolAddress((void**)&wvl, g_wvl);
    cudaGetSymbolAddress((void**)&woh, g_woh);   cudaGetSymbolAddress((void**)&wol, g_wol);
    cudaGetSymbolAddress((void**)&Qh, g_Qh);     cudaGetSymbolAddress((void**)&Ql, g_Ql);
    cudaGetSymbolAddress((void**)&Kh, g_Kh);     cudaGetSymbolAddress((void**)&Kl, g_Kl);
    cudaGetSymbolAddress((void**)&Vh, g_Vh);     cudaGetSymbolAddress((void**)&Vl, g_Vl);
    cudaGetSymbolAddress((void**)&ctxh, g_ctxh); cudaGetSymbolAddress((void**)&ctxl, g_ctxl);
    cudaGetSymbolAddress((void**)&Qf, g_Q);

    const int nIn = SEQ * ND / 1024;
    const int nW  = ND * ND / 1024;

    split3_kernel<<<dim3(nIn, 3), 256>>>(q, k, v,
                                         inqh, inql, inkh, inkl, invh, invl);
    split4_kernel<<<dim3(nW, 4), 256>>>(Wq_w, Wk_w, Wv_w, Wo_w,
                                        wqh, wql, wkh, wkl, wvh, wvl, woh, wol);

    dim3 gProj(ND / 64, SEQ / 128);   // (16, 16) = 256 CTAs
    mm_bias_kernel<<<gProj, 256, MM_SMEM>>>(inqh, inql, wqh, wql, Wq_b, Qf, Qh, Ql);
    mm_bias_kernel<<<gProj, 256, MM_SMEM>>>(inkh, inkl, wkh, wkl, Wk_b, nullptr, Kh, Kl);
    mm_bias_kernel<<<gProj, 256, MM_SMEM>>>(invh, invl, wvh, wvl, Wv_b, nullptr, Vh, Vl);

    qk_kernel<<<dim3(SEQ / 128, SEQ / 128, NH), 256, QK_SMEM>>>();
    li_kernel<<<dim3(SEQ / 64, NH), 256>>>(pos_emb);
    cope_softmax_kernel<<<dim3(SEQ, NH), 256>>>();
    ctx_kernel<<<dim3(SEQ / 128, NH), 256, CX_SMEM>>>();

    mm_bias_kernel<<<gProj, 256, MM_SMEM>>>(ctxh, ctxl, woh, wol, Wo_b, out, nullptr, nullptr);
}